// round 6
// baseline (speedup 1.0000x reference)
#include <cuda_runtime.h>
#include <cstdint>

#define DV 16
#define HV 64
#define WV 64
#define NVOX (DV*HV*WV)   /* 65536 voxels */
#define JP   64           /* padded channel count (>= J=55) */

// Scratch (no allocations allowed)
__device__ __align__(16) float g_vol_t[NVOX * JP];     // 16 MB: [voxel][JP]
__device__ int g_mask_is_u8;                           // runtime mask-dtype flag

// ---------------------------------------------------------------------------
// mask dtype detection: int32 0/1 has zero bytes at offsets %4!=0; u8 doesn't.
// ---------------------------------------------------------------------------
__global__ void reset_flag_kernel() { g_mask_is_u8 = 0; }

__global__ void detect_mask_kernel(const unsigned char* __restrict__ m, int N) {
    int i = blockIdx.x * 256 + threadIdx.x;
    int limit = N < 65536 ? N : 65536;
    if (i < limit && (i & 3) != 0 && m[i] != 0)
        atomicOr(&g_mask_is_u8, 1);
}

// ---------------------------------------------------------------------------
// Kernel 1: vol [J][D][H][W] -> g_vol_t [D*H*W][JP] (channel-contiguous, padded)
// ---------------------------------------------------------------------------
__global__ void __launch_bounds__(256) transpose_vol_kernel(const float* __restrict__ vol, int J) {
    __shared__ float tile[64][65];
    int v0 = blockIdx.x * 64;
    #pragma unroll
    for (int e = threadIdx.x; e < 64 * 64; e += 256) {
        int j = e >> 6, vi = e & 63;
        tile[j][vi] = (j < J) ? vol[j * NVOX + v0 + vi] : 0.0f;
    }
    __syncthreads();
    #pragma unroll
    for (int e = threadIdx.x; e < 64 * 64; e += 256) {
        int vi = e >> 6, j = e & 63;
        g_vol_t[(v0 + vi) * JP + j] = tile[j][vi];
    }
}

// ---------------------------------------------------------------------------
// packed f32x2 helpers
// ---------------------------------------------------------------------------
static __device__ __forceinline__ unsigned long long ffma2(
    unsigned long long a, unsigned long long b, unsigned long long c) {
    unsigned long long d;
    asm("fma.rn.f32x2 %0, %1, %2, %3;" : "=l"(d) : "l"(a), "l"(b), "l"(c));
    return d;
}
static __device__ __forceinline__ unsigned long long splat2(float w) {
    unsigned long long d;
    asm("mov.b64 %0, {%1, %1};" : "=l"(d) : "f"(w));
    return d;
}
static __device__ __forceinline__ float2 u2f2(unsigned long long v) {
    float2 r;
    asm("mov.b64 {%0, %1}, %2;" : "=f"(r.x), "=f"(r.y) : "l"(v));
    return r;
}
static __device__ __forceinline__ float4 fma4(float a, float4 b, float4 c) {
    float4 r;
    r.x = fmaf(a, b.x, c.x); r.y = fmaf(a, b.y, c.y);
    r.z = fmaf(a, b.z, c.z); r.w = fmaf(a, b.w, c.w);
    return r;
}

// Accumulate weight WW times tfs_inv / tfs row-block (T = j*4 in float4 units)
#define ACCW(WW, T) do {                                                       \
    unsigned long long w2 = splat2(WW);                                        \
    ulonglong2 ti0 = *(const ulonglong2*)&s_ti[(T)+0];                         \
    ulonglong2 ti1 = *(const ulonglong2*)&s_ti[(T)+1];                         \
    ulonglong2 ti2 = *(const ulonglong2*)&s_ti[(T)+2];                         \
    ulonglong2 ti3 = *(const ulonglong2*)&s_ti[(T)+3];                         \
    A[0]=ffma2(w2,ti0.x,A[0]); A[1]=ffma2(w2,ti0.y,A[1]);                      \
    A[2]=ffma2(w2,ti1.x,A[2]); A[3]=ffma2(w2,ti1.y,A[3]);                      \
    A[4]=ffma2(w2,ti2.x,A[4]); A[5]=ffma2(w2,ti2.y,A[5]);                      \
    A[6]=ffma2(w2,ti3.x,A[6]); A[7]=ffma2(w2,ti3.y,A[7]);                      \
    ulonglong2 tf0 = *(const ulonglong2*)&s_tf[(T)+0];                         \
    ulonglong2 tf1 = *(const ulonglong2*)&s_tf[(T)+1];                         \
    ulonglong2 tf2 = *(const ulonglong2*)&s_tf[(T)+2];                         \
    ulonglong2 tf3 = *(const ulonglong2*)&s_tf[(T)+3];                         \
    C[0]=ffma2(w2,tf0.x,C[0]); C[1]=ffma2(w2,tf0.y,C[1]);                      \
    C[2]=ffma2(w2,tf1.x,C[2]); C[3]=ffma2(w2,tf1.y,C[3]);                      \
    C[4]=ffma2(w2,tf2.x,C[4]); C[5]=ffma2(w2,tf2.y,C[5]);                      \
    C[6]=ffma2(w2,tf3.x,C[6]); C[7]=ffma2(w2,tf3.y,C[7]); } while(0)

#define NWRP 4

// ---------------------------------------------------------------------------
// Kernel 2: fused deformer. 128 threads = 4 warps; each warp owns 32 points.
// Phase 1a: cooperative trilinear gather for unmasked points -> s_ws
// Phase 1b: bit-iterated coalesced lbsw row loads for masked points -> s_ws
// Phase 2:  branch-free packed-f32x2 blend with tfs/tfs_inv in shared memory.
// s_ws layout swizzled: chunk c, point p lives at float4 slot [c*32 + ((p+c)&31)]
// ---------------------------------------------------------------------------
__global__ void __launch_bounds__(128, 5) deform_kernel(
    const float* __restrict__ xc, const float* __restrict__ shape_off,
    const float* __restrict__ pose_off, const float* __restrict__ tfs,
    const float* __restrict__ tfs_inv, const float* __restrict__ poseoff_ori,
    const void* __restrict__ mask_raw, const float* __restrict__ lbsw,
    const float* __restrict__ offk, const float* __restrict__ sclk,
    float* __restrict__ out_xd, float* __restrict__ out_w,
    int N, int J)
{
    const int b = blockIdx.y;
    __shared__ float4 s_ti[56 * 4];            // tfs_inv rows (row j=55 zeroed)
    __shared__ float4 s_tf[56 * 4];            // tfs[b] rows
    __shared__ float4 s_ws[NWRP][14 * 32];     // staged weights, swizzled
    __shared__ uint4  s_pk[NWRP][32];          // packed corner voxel idx (4xu16 even | 4xu16 odd)
    __shared__ float4 s_pf[NWRP][32];          // (wx, wy, wz, -)

    {
        float* sti = (float*)s_ti;
        float* stf = (float*)s_tf;
        for (int e = threadIdx.x; e < 56 * 16; e += 128) {
            int j = e >> 4, k = e & 15;
            sti[e] = (j < J) ? tfs_inv[j * 16 + k] : 0.0f;
            stf[e] = (j < J) ? tfs[(b * J + j) * 16 + k] : 0.0f;
        }
    }
    __syncthreads();

    const int warp = threadIdx.x >> 5;
    const int lane = threadIdx.x & 31;
    const int wbase = (blockIdx.x * NWRP + warp) * 32;
    const int n  = wbase + lane;
    const int nc = n < N ? n : N - 1;          // clamp; no early return (warp ops!)
    const long idx = (long)b * N + nc;

    // ----- per-point setup -----
    bool msk;
    if (g_mask_is_u8) msk = (((const unsigned char*)mask_raw)[nc] != 0);
    else              msk = (((const int*)mask_raw)[nc] != 0);
    const unsigned mbits = __ballot_sync(0xffffffffu, msk);

    const float px = xc[idx * 3 + 0], py = xc[idx * 3 + 1], pz = xc[idx * 3 + 2];
    const float fx = (px + offk[0]) * sclk[0];
    const float fy = (py + offk[1]) * sclk[1];
    const float fz = (pz + offk[2]) * sclk[2];

    float ix = fminf(fmaxf((fx + 1.0f) * 0.5f * (float)(WV - 1), 0.0f), (float)(WV - 1));
    float iy = fminf(fmaxf((fy + 1.0f) * 0.5f * (float)(HV - 1), 0.0f), (float)(HV - 1));
    float iz = fminf(fmaxf((fz + 1.0f) * 0.5f * (float)(DV - 1), 0.0f), (float)(DV - 1));
    float xf = floorf(ix), yf = floorf(iy), zf = floorf(iz);
    float wx = ix - xf, wy = iy - yf, wz = iz - zf;
    int x0 = (int)xf, y0 = (int)yf, z0 = (int)zf;
    int x1 = min(x0 + 1, WV - 1), y1 = min(y0 + 1, HV - 1), z1 = min(z0 + 1, DV - 1);

    int r00 = (z0 * HV + y0) * WV, r01 = (z0 * HV + y1) * WV;
    int r10 = (z1 * HV + y0) * WV, r11 = (z1 * HV + y1) * WV;

    {   // stage packed voxel indices (fit u16) and fraction triple
        unsigned e0 = (unsigned)(r00 + x0) | ((unsigned)(r01 + x0) << 16);
        unsigned e1 = (unsigned)(r10 + x0) | ((unsigned)(r11 + x0) << 16);
        unsigned o0 = (unsigned)(r00 + x1) | ((unsigned)(r01 + x1) << 16);
        unsigned o1 = (unsigned)(r10 + x1) | ((unsigned)(r11 + x1) << 16);
        s_pk[warp][lane] = make_uint4(e0, e1, o0, o1);
        s_pf[warp][lane] = make_float4(wx, wy, wz, 0.0f);
    }
    __syncwarp();

    // ----- phase 1a: cooperative gather for unmasked points -----
    const float4* vt4 = (const float4*)g_vol_t;
    float4* ws4 = s_ws[warp];
    const int c = lane & 15;          // float4 chunk handled by this lane (0..13 real)
    const int half = lane >> 4;       // 0: x0 corners, 1: x1 corners
    const bool active = (c < 14);

    if (mbits != 0xffffffffu) {
        #pragma unroll 2
        for (int p = 0; p < 32; ++p) {
            if ((mbits >> p) & 1u) continue;          // warp-uniform branch
            const uint2* pk2 = (const uint2*)&s_pk[warp][p];
            uint2 e = pk2[half];                      // this half's 4 voxel idx
            float4 wv = s_pf[warp][p];                // (wx, wy, wz)
            float xl = half ? wv.x : 1.0f - wv.x;
            float t0 = (1.0f - wv.z) * xl, t1 = wv.z * xl;
            float myy = 1.0f - wv.y;
            float w0 = t0 * myy, w1 = t0 * wv.y, w2 = t1 * myy, w3 = t1 * wv.y;

            float4 acc = make_float4(0.f, 0.f, 0.f, 0.f);
            if (active) {
                float4 v0 = vt4[(e.x & 0xffffu) * 16 + c];
                float4 v1 = vt4[(e.x >> 16) * 16 + c];
                float4 v2 = vt4[(e.y & 0xffffu) * 16 + c];
                float4 v3 = vt4[(e.y >> 16) * 16 + c];
                acc = fma4(w0, v0, acc); acc = fma4(w1, v1, acc);
                acc = fma4(w2, v2, acc); acc = fma4(w3, v3, acc);
            }
            acc.x += __shfl_xor_sync(0xffffffffu, acc.x, 16);
            acc.y += __shfl_xor_sync(0xffffffffu, acc.y, 16);
            acc.z += __shfl_xor_sync(0xffffffffu, acc.z, 16);
            acc.w += __shfl_xor_sync(0xffffffffu, acc.w, 16);
            if (active && half == 0) ws4[c * 32 + ((p + c) & 31)] = acc;
        }
    }

    // ----- phase 1b: masked points, coalesced lbsw rows -----
    {
        float* wsf = (float*)ws4;
        const int j1 = lane;                      // 0..31  (< J always)
        const int j2 = lane + 32;                 // 32..63 (guard < 56)
        const int c1 = j1 >> 2, k1 = j1 & 3;
        const int c2 = j2 >> 2, k2 = j2 & 3;
        for (unsigned rem = mbits; rem; rem &= rem - 1) {
            int p = __ffs(rem) - 1;
            int np = wbase + p;
            if (np >= N) continue;
            const float* row = lbsw + (long)np * J;
            wsf[(c1 * 32 + ((p + c1) & 31)) * 4 + k1] = row[j1];
            if (j2 < 56)
                wsf[(c2 * 32 + ((p + c2) & 31)) * 4 + k2] = (j2 < J) ? row[j2] : 0.0f;
        }
    }
    __syncwarp();

    // ----- phase 2: branch-free packed-f32x2 blend -----
    unsigned long long A[8], C[8];
    #pragma unroll
    for (int i = 0; i < 8; ++i) { A[i] = 0ull; C[i] = 0ull; }

    #pragma unroll
    for (int cc = 0; cc < 14; ++cc) {
        float4 w4 = ws4[cc * 32 + ((lane + cc) & 31)];
        int t = cc * 16;
        ACCW(w4.x, t);      ACCW(w4.y, t + 4);
        ACCW(w4.z, t + 8);  ACCW(w4.w, t + 12);
    }

    float2 a0l = u2f2(A[0]), a0h = u2f2(A[1]);
    float2 a1l = u2f2(A[2]), a1h = u2f2(A[3]);
    float2 a2l = u2f2(A[4]), a2h = u2f2(A[5]);
    float2 a3l = u2f2(A[6]), a3h = u2f2(A[7]);
    float4 A0 = {a0l.x, a0l.y, a0h.x, a0h.y};
    float4 A1 = {a1l.x, a1l.y, a1h.x, a1h.y};
    float4 A2 = {a2l.x, a2l.y, a2h.x, a2h.y};
    float4 A3 = {a3l.x, a3l.y, a3h.x, a3h.y};
    float2 c0l = u2f2(C[0]), c0h = u2f2(C[1]);
    float2 c1l = u2f2(C[2]), c1h = u2f2(C[3]);
    float2 c2l = u2f2(C[4]), c2h = u2f2(C[5]);
    float2 c3l = u2f2(C[6]), c3h = u2f2(C[7]);
    float4 C0 = {c0l.x, c0l.y, c0h.x, c0h.y};
    float4 C1 = {c1l.x, c1l.y, c1h.x, c1h.y};
    float4 C2 = {c2l.x, c2l.y, c2h.x, c2h.y};
    float4 C3 = {c3l.x, c3l.y, c3h.x, c3h.y};

    // xc_cano = w_tf_inv @ [xc, 1]
    float cx = A0.x * px + A0.y * py + A0.z * pz + A0.w;
    float cy = A1.x * px + A1.y * py + A1.z * pz + A1.w;
    float cz = A2.x * px + A2.y * py + A2.z * pz + A2.w;

    const long n3 = (long)nc * 3, i3 = idx * 3;
    float sx = cx - poseoff_ori[n3 + 0] + shape_off[i3 + 0] + pose_off[i3 + 0];
    float sy = cy - poseoff_ori[n3 + 1] + shape_off[i3 + 1] + pose_off[i3 + 1];
    float sz = cz - poseoff_ori[n3 + 2] + shape_off[i3 + 2] + pose_off[i3 + 2];

    if (n < N) {
        out_xd[i3 + 0] = C0.x * sx + C0.y * sy + C0.z * sz + C0.w;
        out_xd[i3 + 1] = C1.x * sx + C1.y * sy + C1.z * sz + C1.w;
        out_xd[i3 + 2] = C2.x * sx + C2.y * sy + C2.z * sz + C2.w;

        float4* ow = ((float4*)out_w) + idx * 4;
        float4 R;
        R.x = C0.x*A0.x + C0.y*A1.x + C0.z*A2.x + C0.w*A3.x;
        R.y = C0.x*A0.y + C0.y*A1.y + C0.z*A2.y + C0.w*A3.y;
        R.z = C0.x*A0.z + C0.y*A1.z + C0.z*A2.z + C0.w*A3.z;
        R.w = C0.x*A0.w + C0.y*A1.w + C0.z*A2.w + C0.w*A3.w;
        ow[0] = R;
        R.x = C1.x*A0.x + C1.y*A1.x + C1.z*A2.x + C1.w*A3.x;
        R.y = C1.x*A0.y + C1.y*A1.y + C1.z*A2.y + C1.w*A3.y;
        R.z = C1.x*A0.z + C1.y*A1.z + C1.z*A2.z + C1.w*A3.z;
        R.w = C1.x*A0.w + C1.y*A1.w + C1.z*A2.w + C1.w*A3.w;
        ow[1] = R;
        R.x = C2.x*A0.x + C2.y*A1.x + C2.z*A2.x + C2.w*A3.x;
        R.y = C2.x*A0.y + C2.y*A1.y + C2.z*A2.y + C2.w*A3.y;
        R.z = C2.x*A0.z + C2.y*A1.z + C2.z*A2.z + C2.w*A3.z;
        R.w = C2.x*A0.w + C2.y*A1.w + C2.z*A2.w + C2.w*A3.w;
        ow[2] = R;
        R.x = C3.x*A0.x + C3.y*A1.x + C3.z*A2.x + C3.w*A3.x;
        R.y = C3.x*A0.y + C3.y*A1.y + C3.z*A2.y + C3.w*A3.y;
        R.z = C3.x*A0.z + C3.y*A1.z + C3.z*A2.z + C3.w*A3.z;
        R.w = C3.x*A0.w + C3.y*A1.w + C3.z*A2.w + C3.w*A3.w;
        ow[3] = R;
    }
}

// ---------------------------------------------------------------------------
// Host: resolve inputs by exact element count (ordering-independent binding).
// ---------------------------------------------------------------------------
extern "C" void kernel_launch(void* const* d_in, const int* in_sizes, int n_in,
                              void* d_out, int out_size) {
    const float *tfs = nullptr, *tfs_inv = nullptr, *poseoff_ori = nullptr,
                *lbsw = nullptr, *vol = nullptr;
    const void  *mask = nullptr;
    const float *p3M[3] = {nullptr, nullptr, nullptr};
    const float *psm[2] = {nullptr, nullptr};
    int c3 = 0, cs = 0;
    int idx_mask = -1, idx_first3M = -1;

    for (int i = 0; i < n_in; i++) {
        switch (in_sizes[i]) {
            case 3520:     tfs = (const float*)d_in[i]; break;
            case 880:      tfs_inv = (const float*)d_in[i]; break;
            case 750000:   poseoff_ori = (const float*)d_in[i]; break;
            case 13750000: lbsw = (const float*)d_in[i]; break;
            case 250000:   mask = d_in[i]; idx_mask = i; break;
            case 3604480:  vol = (const float*)d_in[i]; break;
            case 3:        if (cs < 2) psm[cs++] = (const float*)d_in[i]; break;
            case 3000000:
                if (c3 == 0) idx_first3M = i;
                if (c3 < 3) p3M[c3++] = (const float*)d_in[i];
                break;
            default: break;
        }
    }

    const int J = 55, N = 250000, B = 4;

    const float* xc        = (idx_mask >= 0 && idx_first3M >= 0 && idx_mask < idx_first3M)
                             ? p3M[2] : p3M[0];
    const float* shape_off = (xc == p3M[0]) ? p3M[1] : p3M[0];
    const float* pose_off  = (xc == p3M[0]) ? p3M[2] : p3M[1];
    const float* offk = psm[0];
    const float* sclk = psm[1];

    float* out_xd = (float*)d_out;
    float* out_w  = out_xd + (size_t)B * N * 3;

    reset_flag_kernel<<<1, 1>>>();
    detect_mask_kernel<<<(65536 + 255) / 256, 256>>>((const unsigned char*)mask, N);
    transpose_vol_kernel<<<NVOX / 64, 256>>>(vol, J);

    dim3 grid((N + 127) / 128, B);
    deform_kernel<<<grid, 128>>>(xc, shape_off, pose_off, tfs, tfs_inv,
                                 poseoff_ori, mask, lbsw, offk, sclk,
                                 out_xd, out_w, N, J);
}